// round 14
// baseline (speedup 1.0000x reference)
#include <cuda_runtime.h>
#include <cuda_bf16.h>
#include <cuda_fp8.h>
#include <cstdint>

// ============================================================================
// out[T,N] = (fp8_rowwise_quant(x) @ W_fp8^T) * in_scale * w_scale + bias
// T=8192, N=4096, K=4096. Target plain sm_103.
// e4m3 QMMA m16n8k32 + f32 acc. R14 = R9 shape (best: 711us GEMM) at
// 3 CTAs/SM (launch_bounds(256,3), regs<=85) -> 6 warps/SMSP for latency
// coverage; mid-window prefetch. Same tile/traffic ratios as R9.
// ============================================================================

#define E4M3_MAX 448.0f

static constexpr int MAX_T = 8192;
static constexpr int MAX_K = 4096;
static constexpr int MAX_N = 4096;

// Scratch (allocation-free rule: __device__ globals)
__device__ __align__(16) unsigned char g_xq[(size_t)MAX_T * MAX_K];  // 32 MB fp8
__device__ __align__(16) unsigned char g_wq[(size_t)MAX_N * MAX_K];  // 16 MB fp8
__device__ float g_scale[MAX_T];

// ----------------------------------------------------------------------------
// Helpers
// ----------------------------------------------------------------------------
__device__ __forceinline__ uint32_t smem_u32(const void* p) {
    uint32_t a;
    asm("{ .reg .u64 t; cvta.to.shared.u64 t, %1; cvt.u32.u64 %0, t; }" : "=r"(a) : "l"(p));
    return a;
}

// 64B-row swizzle: offset bits [5:4] ^= bits [8:7]
#define SWZ64(x) ((x) ^ (((x) >> 3) & 0x30))

#define CP_ASYNC16(dst, src) \
    asm volatile("cp.async.cg.shared.global [%0], [%1], 16;" :: "r"(dst), "l"(src) : "memory")
#define CP_ASYNC_COMMIT() asm volatile("cp.async.commit_group;" ::: "memory")
#define CP_ASYNC_WAIT2()  asm volatile("cp.async.wait_group 2;" ::: "memory")

#define LDSM_X4(r0, r1, r2, r3, addr) \
    asm volatile("ldmatrix.sync.aligned.m8n8.x4.shared.b16 {%0,%1,%2,%3}, [%4];" \
        : "=r"(r0), "=r"(r1), "=r"(r2), "=r"(r3) : "r"(addr))

#define MMA_E4M3(d, a0, a1, a2, a3, b0, b1) \
    asm volatile("mma.sync.aligned.m16n8k32.row.col.f32.e4m3.e4m3.f32 " \
        "{%0,%1,%2,%3}, {%4,%5,%6,%7}, {%8,%9}, {%0,%1,%2,%3};" \
        : "+f"((d)[0]), "+f"((d)[1]), "+f"((d)[2]), "+f"((d)[3]) \
        : "r"(a0), "r"(a1), "r"(a2), "r"(a3), "r"(b0), "r"(b1))

__device__ __forceinline__ uint32_t f2_to_fp8x2(float a, float b) {
    return (uint32_t)__nv_cvt_float2_to_fp8x2(make_float2(a, b), __NV_SATFINITE, __NV_E4M3);
}

// Probe W dtype from its first 64 elements (e4m3 values are exact in f32/bf16).
__device__ __forceinline__ int probe_wfmt(const unsigned char* __restrict__ w) {
    const uint32_t* p32 = reinterpret_cast<const uint32_t*>(w);
    bool f32ok = true;
    #pragma unroll 4
    for (int i = 0; i < 64; i++) {
        uint32_t b = p32[i];
        float a = fabsf(__uint_as_float(b));
        if (a != 0.0f) {
            if ((b & 0xFFFFFu) != 0u || a > 448.0f || a < 0.001953125f) { f32ok = false; break; }
        }
    }
    if (f32ok) return 1;
    const uint16_t* p16 = reinterpret_cast<const uint16_t*>(w);
    bool bf16ok = true;
    #pragma unroll 4
    for (int i = 0; i < 64; i++) {
        uint16_t b = p16[i];
        uint16_t m = (uint16_t)(b & 0x7FFFu);
        if (m != 0) {
            if ((b & 0xFu) != 0u || m > 0x43E0u || m < 0x3B00u) { bf16ok = false; break; }
        }
    }
    return bf16ok ? 2 : 0;
}

// ----------------------------------------------------------------------------
// Fused prep kernel: blocks [0, T) quantize x rows; blocks [T, T+nR) repack W.
// ----------------------------------------------------------------------------
__global__ void __launch_bounds__(256) prep_kernel(const float* __restrict__ x,
                                                   const unsigned char* __restrict__ w,
                                                   int K, int T) {
    const int tid = threadIdx.x;

    if ((int)blockIdx.x < T) {
        const int t = blockIdx.x;
        const float4* xr = reinterpret_cast<const float4*>(x + (size_t)t * K);

        float4 v[4];
        float amax = 0.f;
        #pragma unroll
        for (int i = 0; i < 4; i++) {
            v[i] = xr[tid + (i << 8)];
            amax = fmaxf(amax, fmaxf(fmaxf(fabsf(v[i].x), fabsf(v[i].y)),
                                     fmaxf(fabsf(v[i].z), fabsf(v[i].w))));
        }
        #pragma unroll
        for (int o = 16; o > 0; o >>= 1)
            amax = fmaxf(amax, __shfl_xor_sync(0xFFFFFFFFu, amax, o));

        __shared__ float red[8];
        __shared__ float s_scale;
        if ((tid & 31) == 0) red[tid >> 5] = amax;
        __syncthreads();
        if (tid < 32) {
            float a = (tid < 8) ? red[tid] : 0.f;
            #pragma unroll
            for (int o = 4; o > 0; o >>= 1)
                a = fmaxf(a, __shfl_xor_sync(0xFFFFFFFFu, a, o));
            if (tid == 0) {
                float s = fmaxf(a / E4M3_MAX, 1e-12f);
                g_scale[t] = s;
                s_scale = s;
            }
        }
        __syncthreads();
        const float s = s_scale;

        uint32_t* dst = reinterpret_cast<uint32_t*>(g_xq) + (size_t)t * (K >> 2);
        #pragma unroll
        for (int i = 0; i < 4; i++) {
            uint32_t p0 = f2_to_fp8x2(v[i].x / s, v[i].y / s);
            uint32_t p1 = f2_to_fp8x2(v[i].z / s, v[i].w / s);
            dst[tid + (i << 8)] = p0 | (p1 << 16);
        }
    } else {
        __shared__ int s_fmt;
        if (tid == 0) s_fmt = probe_wfmt(w);
        __syncthreads();
        const int fmt = s_fmt;

        const size_t i = (size_t)(blockIdx.x - T) * 256 + tid;  // 16-elem group
        uint4 o;
        if (fmt == 1) {
            const float4* sp = reinterpret_cast<const float4*>(w) + 4 * i;
            float4 f0 = sp[0], f1 = sp[1], f2 = sp[2], f3 = sp[3];
            o.x = f2_to_fp8x2(f0.x, f0.y) | (f2_to_fp8x2(f0.z, f0.w) << 16);
            o.y = f2_to_fp8x2(f1.x, f1.y) | (f2_to_fp8x2(f1.z, f1.w) << 16);
            o.z = f2_to_fp8x2(f2.x, f2.y) | (f2_to_fp8x2(f2.z, f2.w) << 16);
            o.w = f2_to_fp8x2(f3.x, f3.y) | (f2_to_fp8x2(f3.z, f3.w) << 16);
        } else if (fmt == 2) {
            const uint4* sp = reinterpret_cast<const uint4*>(w) + 2 * i;
            uint4 b0 = sp[0], b1 = sp[1];
            const __nv_bfloat162* h0 = reinterpret_cast<const __nv_bfloat162*>(&b0);
            const __nv_bfloat162* h1 = reinterpret_cast<const __nv_bfloat162*>(&b1);
            float2 f;
            uint32_t r[8];
            #pragma unroll
            for (int j = 0; j < 4; j++) { f = __bfloat1622float2(h0[j]); r[j]     = f2_to_fp8x2(f.x, f.y); }
            #pragma unroll
            for (int j = 0; j < 4; j++) { f = __bfloat1622float2(h1[j]); r[4 + j] = f2_to_fp8x2(f.x, f.y); }
            o.x = r[0] | (r[1] << 16);
            o.y = r[2] | (r[3] << 16);
            o.z = r[4] | (r[5] << 16);
            o.w = r[6] | (r[7] << 16);
        } else {
            o = reinterpret_cast<const uint4*>(w)[i];
        }
        reinterpret_cast<uint4*>(g_wq)[i] = o;
    }
}

// ----------------------------------------------------------------------------
// Kernel 2: fp8 QMMA GEMM. 128x128 tile, BK=64 fp8 (64B rows), 4-stage
// cp.async pipeline, 256 threads = 8 warps (2m x 4n), warp tile 64x32,
// 3 CTAs/SM (regs capped ~85) -> 6 warps/SMSP.
// ----------------------------------------------------------------------------
static constexpr int F_STAGES = 4;
static constexpr int F_AST    = 128 * 64;                   // 8192 B/stage
static constexpr int F_SA     = 0;
static constexpr int F_SB     = F_STAGES * F_AST;           // 32768
static constexpr int F_SWS    = F_SB + F_STAGES * F_AST;    // 65536
static constexpr int F_SBIAS  = F_SWS + 512;                // 66048
static constexpr int F_SMEM   = F_SBIAS + 512;              // 66560

__global__ void __launch_bounds__(256, 3) mma_gemm_kernel(
    const float* __restrict__ wscale,
    const float* __restrict__ bias,
    float* __restrict__ out,
    int T, int N, int K)
{
    extern __shared__ char smem[];
    const uint32_t sbase = smem_u32(smem);
    const int tid = threadIdx.x, lane = tid & 31, wid = tid >> 5;
    const int n0 = blockIdx.x * 128, m0 = blockIdx.y * 128;
    const int m_off = (wid >> 2) * 64;   // 0 / 64
    const int n_off = (wid & 3) * 32;    // 0 / 32 / 64 / 96

    if (tid < 128) {
        reinterpret_cast<float*>(smem + F_SWS)[tid]   = wscale[n0 + tid];
        reinterpret_cast<float*>(smem + F_SBIAS)[tid] = bias[n0 + tid];
    }

    const unsigned char* aG = g_xq + (size_t)m0 * K;
    const unsigned char* bG = g_wq + (size_t)n0 * K;

    // ldmatrix x4 base addresses for ko=0; ko=1 is base ^ 32
    // (SWZ64(x+32) == SWZ64(x)^32: bit 5 of the unswizzled base is 0).
    const int rsel = lane & 15;
    const int csel = (lane >> 4) * 16;
    uint32_t preA[4], preB[2];
    #pragma unroll
    for (int mt = 0; mt < 4; mt++)
        preA[mt] = sbase + F_SA +
            SWZ64((uint32_t)((m_off + mt * 16 + rsel) * 64 + csel));
    #pragma unroll
    for (int bp = 0; bp < 2; bp++)
        preB[bp] = sbase + F_SB +
            SWZ64((uint32_t)((n_off + bp * 16 + rsel) * 64 + csel));

    float acc[4][4][4];
    #pragma unroll
    for (int i = 0; i < 4; i++)
        #pragma unroll
        for (int j = 0; j < 4; j++)
            #pragma unroll
            for (int q = 0; q < 4; q++) acc[i][j][q] = 0.f;

    const int cchunk = tid & 3;       // 16B chunk within 64B row
    const int crow   = tid >> 2;      // 0..63
    const uint32_t so0 = SWZ64((uint32_t)(crow * 64 + cchunk * 16));
    const uint32_t so1 = SWZ64((uint32_t)((crow + 64) * 64 + cchunk * 16));
    const unsigned char* aP = aG + (size_t)crow * K + cchunk * 16;
    const unsigned char* bP = bG + (size_t)crow * K + cchunk * 16;
    const size_t rowK64 = (size_t)64 * K;

    auto load_stage = [&](int st, int kt) {
        const uint32_t dA = sbase + F_SA + (uint32_t)st * F_AST;
        const uint32_t dB = sbase + F_SB + (uint32_t)st * F_AST;
        const size_t g = (size_t)kt * 64;
        CP_ASYNC16(dA + so0, aP + g);
        CP_ASYNC16(dA + so1, aP + g + rowK64);
        CP_ASYNC16(dB + so0, bP + g);
        CP_ASYNC16(dB + so1, bP + g + rowK64);
    };

    auto compute_half = [&](uint32_t stOff, int ko) {
        const uint32_t koX = (uint32_t)(ko << 5);   // XOR 32 selects k-half
        uint32_t b[4][2];
        #pragma unroll
        for (int bp = 0; bp < 2; bp++) {
            uint32_t r0, r1, r2, r3;
            LDSM_X4(r0, r1, r2, r3, (preB[bp] ^ koX) + stOff);
            b[2*bp][0]   = r0; b[2*bp][1]   = r2;
            b[2*bp+1][0] = r1; b[2*bp+1][1] = r3;
        }
        #pragma unroll
        for (int mt = 0; mt < 4; mt++) {
            uint32_t a0, a1, a2, a3;
            LDSM_X4(a0, a1, a2, a3, (preA[mt] ^ koX) + stOff);
            #pragma unroll
            for (int nt = 0; nt < 4; nt++)
                MMA_E4M3(acc[mt][nt], a0, a1, a2, a3, b[nt][0], b[nt][1]);
        }
    };

    const int KT = K >> 6;  // 64 chunks of 64 fp8
    load_stage(0, 0); CP_ASYNC_COMMIT();
    load_stage(1, 1); CP_ASYNC_COMMIT();
    load_stage(2, 2); CP_ASYNC_COMMIT();

    #pragma unroll 4
    for (int kt = 0; kt < KT; kt++) {
        CP_ASYNC_WAIT2();
        __syncthreads();   // stage kt ready; all warps consumed stage kt-1
        const uint32_t stOff = (uint32_t)(kt & 3) * F_AST;  // immediate after unroll

        compute_half(stOff, 0);
        // Mid-window prefetch: loads start earlier, LSU pressure spread.
        if (kt + 3 < KT) load_stage((kt + 3) & 3, kt + 3);
        compute_half(stOff, 1);
        CP_ASYNC_COMMIT();
    }

    // Epilogue: acc * in_scale[row] * w_scale[col] + bias[col]
    const float* sWSp = reinterpret_cast<const float*>(smem + F_SWS);
    const float* sBiP = reinterpret_cast<const float*>(smem + F_SBIAS);
    #pragma unroll
    for (int mt = 0; mt < 4; mt++) {
        const int r0g = m0 + m_off + mt * 16 + (lane >> 2);
        const int r1g = r0g + 8;
        const float i0 = g_scale[r0g];
        const float i1 = g_scale[r1g];
        float* o0 = out + (size_t)r0g * N + n0;
        float* o1 = out + (size_t)r1g * N + n0;
        #pragma unroll
        for (int nt = 0; nt < 4; nt++) {
            const int c = n_off + nt * 8 + (lane & 3) * 2;
            const float ws0 = sWSp[c], ws1 = sWSp[c + 1];
            const float bb0 = sBiP[c], bb1 = sBiP[c + 1];
            float2 v0 = make_float2(acc[mt][nt][0] * i0 * ws0 + bb0,
                                    acc[mt][nt][1] * i0 * ws1 + bb1);
            float2 v1 = make_float2(acc[mt][nt][2] * i1 * ws0 + bb0,
                                    acc[mt][nt][3] * i1 * ws1 + bb1);
            *reinterpret_cast<float2*>(o0 + c) = v0;
            *reinterpret_cast<float2*>(o1 + c) = v1;
        }
    }
}

// ----------------------------------------------------------------------------
// Launch
// ----------------------------------------------------------------------------
extern "C" void kernel_launch(void* const* d_in, const int* in_sizes, int n_in,
                              void* d_out, int out_size) {
    const float*         x      = (const float*)d_in[0];
    const unsigned char* wraw   = (const unsigned char*)d_in[1];
    const float*         wscale = (const float*)d_in[2];
    const float*         bias   = (const float*)d_in[3];
    float*               out    = (float*)d_out;

    const int N = in_sizes[2];                     // 4096
    const int K = in_sizes[1] / N;                 // 4096
    const int T = (int)((size_t)in_sizes[0] / K);  // 8192

    const unsigned nRepack = (unsigned)(((size_t)N * K) / 16 / 256);  // 4096
    prep_kernel<<<(unsigned)T + nRepack, 256>>>(x, wraw, K, T);

    cudaFuncSetAttribute(mma_gemm_kernel, cudaFuncAttributeMaxDynamicSharedMemorySize, F_SMEM);
    dim3 grid(N / 128, T / 128);
    mma_gemm_kernel<<<grid, 256, F_SMEM>>>(wscale, bias, out, T, N, K);
}

// round 15
// speedup vs baseline: 1.7095x; 1.7095x over previous
#include <cuda_runtime.h>
#include <cuda_bf16.h>
#include <cuda_fp8.h>
#include <cstdint>

// ============================================================================
// out[T,N] = (fp8_rowwise_quant(x) @ W_fp8^T) * in_scale * w_scale + bias
// T=8192, N=4096, K=4096. Target plain sm_103.
// e4m3 QMMA m16n8k32 + f32 acc. R15 = R9 shape (best: 711us GEMM) with the
// block-wide __syncthreads pipeline replaced by an mbarrier producer/consumer
// pipeline (6 stages, full: cp.async-tracked count=256, empty: per-warp
// count=8). Warps drift up to 3 iterations -> LDSM/MMA bursts de-clump.
// ============================================================================

#define E4M3_MAX 448.0f

static constexpr int MAX_T = 8192;
static constexpr int MAX_K = 4096;
static constexpr int MAX_N = 4096;

// Scratch (allocation-free rule: __device__ globals)
__device__ __align__(16) unsigned char g_xq[(size_t)MAX_T * MAX_K];  // 32 MB fp8
__device__ __align__(16) unsigned char g_wq[(size_t)MAX_N * MAX_K];  // 16 MB fp8
__device__ float g_scale[MAX_T];

// ----------------------------------------------------------------------------
// Helpers
// ----------------------------------------------------------------------------
__device__ __forceinline__ uint32_t smem_u32(const void* p) {
    uint32_t a;
    asm("{ .reg .u64 t; cvta.to.shared.u64 t, %1; cvt.u32.u64 %0, t; }" : "=r"(a) : "l"(p));
    return a;
}

// 64B-row swizzle: offset bits [5:4] ^= bits [8:7]
#define SWZ64(x) ((x) ^ (((x) >> 3) & 0x30))

#define CP_ASYNC16(dst, src) \
    asm volatile("cp.async.cg.shared.global [%0], [%1], 16;" :: "r"(dst), "l"(src) : "memory")

// Arrive-on: mbarrier completes this thread's arrival once all its prior
// cp.async ops have completed. .noinc: expected count pre-set at init.
#define CP_ASYNC_MBAR_ARRIVE(mbar) \
    asm volatile("cp.async.mbarrier.arrive.noinc.shared.b64 [%0];" :: "r"(mbar) : "memory")

#define MBARRIER_INIT(addr, cnt) \
    asm volatile("mbarrier.init.shared.b64 [%0], %1;" :: "r"((uint32_t)(addr)), "r"((uint32_t)(cnt)) : "memory")

#define MBARRIER_ARRIVE(addr) \
    asm volatile("mbarrier.arrive.shared.b64 _, [%0];" :: "r"((uint32_t)(addr)) : "memory")

#define MBARRIER_WAIT_PARITY(mbar_smem_addr, phase_parity) do { \
    uint32_t _mbar = (uint32_t)(mbar_smem_addr); \
    uint32_t _parity = (uint32_t)(phase_parity); \
    uint32_t _done; \
    asm volatile( \
        "{\n\t.reg .pred p;\n\t" \
        "mbarrier.try_wait.parity.acquire.cta.shared::cta.b64 p, [%1], %2;\n\t" \
        "selp.b32 %0, 1, 0, p;\n\t}" \
        : "=r"(_done) : "r"(_mbar), "r"(_parity) : "memory"); \
    if (!_done) { \
        asm volatile( \
            "{\n\t.reg .pred P1;\n\t" \
            "WAIT_LOOP_%=:\n\t" \
            "mbarrier.try_wait.parity.acquire.cta.shared::cta.b64 P1, [%0], %1, 0x989680;\n\t" \
            "@P1 bra.uni WAIT_DONE_%=;\n\t" \
            "bra.uni WAIT_LOOP_%=;\n\t" \
            "WAIT_DONE_%=:\n\t}" \
            :: "r"(_mbar), "r"(_parity) : "memory"); \
    } \
} while(0)

#define LDSM_X4(r0, r1, r2, r3, addr) \
    asm volatile("ldmatrix.sync.aligned.m8n8.x4.shared.b16 {%0,%1,%2,%3}, [%4];" \
        : "=r"(r0), "=r"(r1), "=r"(r2), "=r"(r3) : "r"(addr))

#define MMA_E4M3(d, a0, a1, a2, a3, b0, b1) \
    asm volatile("mma.sync.aligned.m16n8k32.row.col.f32.e4m3.e4m3.f32 " \
        "{%0,%1,%2,%3}, {%4,%5,%6,%7}, {%8,%9}, {%0,%1,%2,%3};" \
        : "+f"((d)[0]), "+f"((d)[1]), "+f"((d)[2]), "+f"((d)[3]) \
        : "r"(a0), "r"(a1), "r"(a2), "r"(a3), "r"(b0), "r"(b1))

__device__ __forceinline__ uint32_t f2_to_fp8x2(float a, float b) {
    return (uint32_t)__nv_cvt_float2_to_fp8x2(make_float2(a, b), __NV_SATFINITE, __NV_E4M3);
}

// Probe W dtype from its first 64 elements (e4m3 values are exact in f32/bf16).
__device__ __forceinline__ int probe_wfmt(const unsigned char* __restrict__ w) {
    const uint32_t* p32 = reinterpret_cast<const uint32_t*>(w);
    bool f32ok = true;
    #pragma unroll 4
    for (int i = 0; i < 64; i++) {
        uint32_t b = p32[i];
        float a = fabsf(__uint_as_float(b));
        if (a != 0.0f) {
            if ((b & 0xFFFFFu) != 0u || a > 448.0f || a < 0.001953125f) { f32ok = false; break; }
        }
    }
    if (f32ok) return 1;
    const uint16_t* p16 = reinterpret_cast<const uint16_t*>(w);
    bool bf16ok = true;
    #pragma unroll 4
    for (int i = 0; i < 64; i++) {
        uint16_t b = p16[i];
        uint16_t m = (uint16_t)(b & 0x7FFFu);
        if (m != 0) {
            if ((b & 0xFu) != 0u || m > 0x43E0u || m < 0x3B00u) { bf16ok = false; break; }
        }
    }
    return bf16ok ? 2 : 0;
}

// ----------------------------------------------------------------------------
// Fused prep kernel: blocks [0, T) quantize x rows; blocks [T, T+nR) repack W.
// ----------------------------------------------------------------------------
__global__ void __launch_bounds__(256) prep_kernel(const float* __restrict__ x,
                                                   const unsigned char* __restrict__ w,
                                                   int K, int T) {
    const int tid = threadIdx.x;

    if ((int)blockIdx.x < T) {
        const int t = blockIdx.x;
        const float4* xr = reinterpret_cast<const float4*>(x + (size_t)t * K);

        float4 v[4];
        float amax = 0.f;
        #pragma unroll
        for (int i = 0; i < 4; i++) {
            v[i] = xr[tid + (i << 8)];
            amax = fmaxf(amax, fmaxf(fmaxf(fabsf(v[i].x), fabsf(v[i].y)),
                                     fmaxf(fabsf(v[i].z), fabsf(v[i].w))));
        }
        #pragma unroll
        for (int o = 16; o > 0; o >>= 1)
            amax = fmaxf(amax, __shfl_xor_sync(0xFFFFFFFFu, amax, o));

        __shared__ float red[8];
        __shared__ float s_scale;
        if ((tid & 31) == 0) red[tid >> 5] = amax;
        __syncthreads();
        if (tid < 32) {
            float a = (tid < 8) ? red[tid] : 0.f;
            #pragma unroll
            for (int o = 4; o > 0; o >>= 1)
                a = fmaxf(a, __shfl_xor_sync(0xFFFFFFFFu, a, o));
            if (tid == 0) {
                float s = fmaxf(a / E4M3_MAX, 1e-12f);
                g_scale[t] = s;
                s_scale = s;
            }
        }
        __syncthreads();
        const float s = s_scale;

        uint32_t* dst = reinterpret_cast<uint32_t*>(g_xq) + (size_t)t * (K >> 2);
        #pragma unroll
        for (int i = 0; i < 4; i++) {
            uint32_t p0 = f2_to_fp8x2(v[i].x / s, v[i].y / s);
            uint32_t p1 = f2_to_fp8x2(v[i].z / s, v[i].w / s);
            dst[tid + (i << 8)] = p0 | (p1 << 16);
        }
    } else {
        __shared__ int s_fmt;
        if (tid == 0) s_fmt = probe_wfmt(w);
        __syncthreads();
        const int fmt = s_fmt;

        const size_t i = (size_t)(blockIdx.x - T) * 256 + tid;  // 16-elem group
        uint4 o;
        if (fmt == 1) {
            const float4* sp = reinterpret_cast<const float4*>(w) + 4 * i;
            float4 f0 = sp[0], f1 = sp[1], f2 = sp[2], f3 = sp[3];
            o.x = f2_to_fp8x2(f0.x, f0.y) | (f2_to_fp8x2(f0.z, f0.w) << 16);
            o.y = f2_to_fp8x2(f1.x, f1.y) | (f2_to_fp8x2(f1.z, f1.w) << 16);
            o.z = f2_to_fp8x2(f2.x, f2.y) | (f2_to_fp8x2(f2.z, f2.w) << 16);
            o.w = f2_to_fp8x2(f3.x, f3.y) | (f2_to_fp8x2(f3.z, f3.w) << 16);
        } else if (fmt == 2) {
            const uint4* sp = reinterpret_cast<const uint4*>(w) + 2 * i;
            uint4 b0 = sp[0], b1 = sp[1];
            const __nv_bfloat162* h0 = reinterpret_cast<const __nv_bfloat162*>(&b0);
            const __nv_bfloat162* h1 = reinterpret_cast<const __nv_bfloat162*>(&b1);
            float2 f;
            uint32_t r[8];
            #pragma unroll
            for (int j = 0; j < 4; j++) { f = __bfloat1622float2(h0[j]); r[j]     = f2_to_fp8x2(f.x, f.y); }
            #pragma unroll
            for (int j = 0; j < 4; j++) { f = __bfloat1622float2(h1[j]); r[4 + j] = f2_to_fp8x2(f.x, f.y); }
            o.x = r[0] | (r[1] << 16);
            o.y = r[2] | (r[3] << 16);
            o.z = r[4] | (r[5] << 16);
            o.w = r[6] | (r[7] << 16);
        } else {
            o = reinterpret_cast<const uint4*>(w)[i];
        }
        reinterpret_cast<uint4*>(g_wq)[i] = o;
    }
}

// ----------------------------------------------------------------------------
// Kernel 2: fp8 QMMA GEMM. 128x128 tile, BK=64 fp8 (64B rows), 6-stage
// mbarrier pipeline (no __syncthreads in mainloop), 256 threads = 8 warps
// (2m x 4n), warp tile 64x32, 2 CTAs/SM.
// ----------------------------------------------------------------------------
static constexpr int F_STAGES = 6;
static constexpr int F_AST    = 128 * 64;                   // 8192 B/stage
static constexpr int F_SA     = 0;
static constexpr int F_SB     = F_STAGES * F_AST;           // 49152
static constexpr int F_SWS    = 2 * F_STAGES * F_AST;       // 98304
static constexpr int F_SBIAS  = F_SWS + 512;                // 98816
static constexpr int F_MBAR   = F_SBIAS + 512;              // 99328 (full[6], empty[6])
static constexpr int F_SMEM   = F_MBAR + 16 * 8;            // 99456

__global__ void __launch_bounds__(256, 2) mma_gemm_kernel(
    const float* __restrict__ wscale,
    const float* __restrict__ bias,
    float* __restrict__ out,
    int T, int N, int K)
{
    extern __shared__ char smem[];
    const uint32_t sbase = smem_u32(smem);
    const int tid = threadIdx.x, lane = tid & 31, wid = tid >> 5;
    const int n0 = blockIdx.x * 128, m0 = blockIdx.y * 128;
    const int m_off = (wid >> 2) * 64;   // 0 / 64
    const int n_off = (wid & 3) * 32;    // 0 / 32 / 64 / 96

    const uint32_t mbF = sbase + F_MBAR;        // full[s]  = mbF + 8s
    const uint32_t mbE = sbase + F_MBAR + 48;   // empty[s] = mbE + 8s

    if (tid < 128) {
        reinterpret_cast<float*>(smem + F_SWS)[tid]   = wscale[n0 + tid];
        reinterpret_cast<float*>(smem + F_SBIAS)[tid] = bias[n0 + tid];
    }
    if (tid == 0) {
        #pragma unroll
        for (int s = 0; s < F_STAGES; s++) {
            MBARRIER_INIT(mbF + 8 * s, 256);  // completed via cp.async arrive-on
            MBARRIER_INIT(mbE + 8 * s, 8);    // one arrive per warp
        }
    }
    __syncthreads();  // mbarrier init + WS/BIAS visible

    const unsigned char* aG = g_xq + (size_t)m0 * K;
    const unsigned char* bG = g_wq + (size_t)n0 * K;

    // ldmatrix x4 base addresses for ko=0; ko=1 is base ^ 32.
    const int rsel = lane & 15;
    const int csel = (lane >> 4) * 16;
    uint32_t preA[4], preB[2];
    #pragma unroll
    for (int mt = 0; mt < 4; mt++)
        preA[mt] = sbase + F_SA +
            SWZ64((uint32_t)((m_off + mt * 16 + rsel) * 64 + csel));
    #pragma unroll
    for (int bp = 0; bp < 2; bp++)
        preB[bp] = sbase + F_SB +
            SWZ64((uint32_t)((n_off + bp * 16 + rsel) * 64 + csel));

    float acc[4][4][4];
    #pragma unroll
    for (int i = 0; i < 4; i++)
        #pragma unroll
        for (int j = 0; j < 4; j++)
            #pragma unroll
            for (int q = 0; q < 4; q++) acc[i][j][q] = 0.f;

    const int cchunk = tid & 3;       // 16B chunk within 64B row
    const int crow   = tid >> 2;      // 0..63
    const uint32_t so0 = SWZ64((uint32_t)(crow * 64 + cchunk * 16));
    const uint32_t so1 = SWZ64((uint32_t)((crow + 64) * 64 + cchunk * 16));
    const unsigned char* aP = aG + (size_t)crow * K + cchunk * 16;
    const unsigned char* bP = bG + (size_t)crow * K + cchunk * 16;
    const size_t rowK64 = (size_t)64 * K;

    auto load_stage = [&](int st, int kt) {
        const uint32_t dA = sbase + F_SA + (uint32_t)st * F_AST;
        const uint32_t dB = sbase + F_SB + (uint32_t)st * F_AST;
        const size_t g = (size_t)kt * 64;
        CP_ASYNC16(dA + so0, aP + g);
        CP_ASYNC16(dA + so1, aP + g + rowK64);
        CP_ASYNC16(dB + so0, bP + g);
        CP_ASYNC16(dB + so1, bP + g + rowK64);
        CP_ASYNC_MBAR_ARRIVE(mbF + 8 * st);
    };

    auto compute_iter = [&](uint32_t stOff) {
        #pragma unroll
        for (int ko = 0; ko < 2; ko++) {
            const uint32_t koX = (uint32_t)(ko << 5);
            uint32_t b[4][2];
            #pragma unroll
            for (int bp = 0; bp < 2; bp++) {
                uint32_t r0, r1, r2, r3;
                LDSM_X4(r0, r1, r2, r3, (preB[bp] ^ koX) + stOff);
                b[2*bp][0]   = r0; b[2*bp][1]   = r2;
                b[2*bp+1][0] = r1; b[2*bp+1][1] = r3;
            }
            #pragma unroll
            for (int mt = 0; mt < 4; mt++) {
                uint32_t a0, a1, a2, a3;
                LDSM_X4(a0, a1, a2, a3, (preA[mt] ^ koX) + stOff);
                #pragma unroll
                for (int nt = 0; nt < 4; nt++)
                    MMA_E4M3(acc[mt][nt], a0, a1, a2, a3, b[nt][0], b[nt][1]);
            }
        }
    };

    const int KT = K >> 6;  // 64 chunks of 64 fp8

    // Prologue: produce chunks 0..2 (first use of stages 0..2 -> no empty wait).
    load_stage(0, 0);
    load_stage(1, 1);
    load_stage(2, 2);

    // Cursors: consumer (stage sc, parity pc = (kt/6)&1),
    // producer for chunk kn=kt+3 (stage sp, pp = (kn/6)&1).
    int sc = 0, pc = 0;
    int sp = 3, pp = 0;

    for (int kt = 0; kt < KT; kt++) {
        // Wait chunk kt's data (write #(kt/6) of stage sc -> parity pc).
        MBARRIER_WAIT_PARITY(mbF + 8 * sc, pc);

        compute_iter((uint32_t)sc * F_AST);

        // This warp is done reading stage sc for this round.
        if (lane == 0) MBARRIER_ARRIVE(mbE + 8 * sc);

        const int kn = kt + 3;
        if (kn < KT) {
            // Reuse q = kn/6 (>=1 iff kn>=6): wait consumption of chunk kn-6,
            // i.e. empty[sp] completion q -> parity (q-1)&1 = pp^1.
            if (kn >= F_STAGES) MBARRIER_WAIT_PARITY(mbE + 8 * sp, pp ^ 1);
            load_stage(sp, kn);
        }

        if (++sc == F_STAGES) { sc = 0; pc ^= 1; }
        if (++sp == F_STAGES) { sp = 0; pp ^= 1; }
    }

    // Epilogue: acc * in_scale[row] * w_scale[col] + bias[col]
    const float* sWSp = reinterpret_cast<const float*>(smem + F_SWS);
    const float* sBiP = reinterpret_cast<const float*>(smem + F_SBIAS);
    #pragma unroll
    for (int mt = 0; mt < 4; mt++) {
        const int r0g = m0 + m_off + mt * 16 + (lane >> 2);
        const int r1g = r0g + 8;
        const float i0 = g_scale[r0g];
        const float i1 = g_scale[r1g];
        float* o0 = out + (size_t)r0g * N + n0;
        float* o1 = out + (size_t)r1g * N + n0;
        #pragma unroll
        for (int nt = 0; nt < 4; nt++) {
            const int c = n_off + nt * 8 + (lane & 3) * 2;
            const float ws0 = sWSp[c], ws1 = sWSp[c + 1];
            const float bb0 = sBiP[c], bb1 = sBiP[c + 1];
            float2 v0 = make_float2(acc[mt][nt][0] * i0 * ws0 + bb0,
                                    acc[mt][nt][1] * i0 * ws1 + bb1);
            float2 v1 = make_float2(acc[mt][nt][2] * i1 * ws0 + bb0,
                                    acc[mt][nt][3] * i1 * ws1 + bb1);
            *reinterpret_cast<float2*>(o0 + c) = v0;
            *reinterpret_cast<float2*>(o1 + c) = v1;
        }
    }
}

// ----------------------------------------------------------------------------
// Launch
// ----------------------------------------------------------------------------
extern "C" void kernel_launch(void* const* d_in, const int* in_sizes, int n_in,
                              void* d_out, int out_size) {
    const float*         x      = (const float*)d_in[0];
    const unsigned char* wraw   = (const unsigned char*)d_in[1];
    const float*         wscale = (const float*)d_in[2];
    const float*         bias   = (const float*)d_in[3];
    float*               out    = (float*)d_out;

    const int N = in_sizes[2];                     // 4096
    const int K = in_sizes[1] / N;                 // 4096
    const int T = (int)((size_t)in_sizes[0] / K);  // 8192

    const unsigned nRepack = (unsigned)(((size_t)N * K) / 16 / 256);  // 4096
    prep_kernel<<<(unsigned)T + nRepack, 256>>>(x, wraw, K, T);

    cudaFuncSetAttribute(mma_gemm_kernel, cudaFuncAttributeMaxDynamicSharedMemorySize, F_SMEM);
    dim3 grid(N / 128, T / 128);
    mma_gemm_kernel<<<grid, 256, F_SMEM>>>(wscale, bias, out, T, N, K);
}

// round 16
// speedup vs baseline: 2.0130x; 1.1775x over previous
#include <cuda_runtime.h>
#include <cuda_bf16.h>
#include <cuda_fp8.h>
#include <cstdint>

// ============================================================================
// out[T,N] = (fp8_rowwise_quant(x) @ W_fp8^T) * in_scale * w_scale + bias
// T=8192, N=4096, K=4096. Target plain sm_103.
// e4m3 QMMA m16n8k32 + f32 acc. R16 = R9 GEMM verbatim (best: 711us) +
// prep polish: __ldcs streaming loads for read-once x / raw W (protects
// L2 residency of g_xq/g_wq for the GEMM), caching stores for scratch.
// ============================================================================

#define E4M3_MAX 448.0f

static constexpr int MAX_T = 8192;
static constexpr int MAX_K = 4096;
static constexpr int MAX_N = 4096;

// Scratch (allocation-free rule: __device__ globals)
__device__ __align__(16) unsigned char g_xq[(size_t)MAX_T * MAX_K];  // 32 MB fp8
__device__ __align__(16) unsigned char g_wq[(size_t)MAX_N * MAX_K];  // 16 MB fp8
__device__ float g_scale[MAX_T];

// ----------------------------------------------------------------------------
// Helpers
// ----------------------------------------------------------------------------
__device__ __forceinline__ uint32_t smem_u32(const void* p) {
    uint32_t a;
    asm("{ .reg .u64 t; cvta.to.shared.u64 t, %1; cvt.u32.u64 %0, t; }" : "=r"(a) : "l"(p));
    return a;
}

// 64B-row swizzle: offset bits [5:4] ^= bits [8:7]
#define SWZ64(x) ((x) ^ (((x) >> 3) & 0x30))

#define CP_ASYNC16(dst, src) \
    asm volatile("cp.async.cg.shared.global [%0], [%1], 16;" :: "r"(dst), "l"(src) : "memory")
#define CP_ASYNC_COMMIT() asm volatile("cp.async.commit_group;" ::: "memory")
#define CP_ASYNC_WAIT2()  asm volatile("cp.async.wait_group 2;" ::: "memory")

#define LDSM_X4(r0, r1, r2, r3, addr) \
    asm volatile("ldmatrix.sync.aligned.m8n8.x4.shared.b16 {%0,%1,%2,%3}, [%4];" \
        : "=r"(r0), "=r"(r1), "=r"(r2), "=r"(r3) : "r"(addr))

#define MMA_E4M3(d, a0, a1, a2, a3, b0, b1) \
    asm volatile("mma.sync.aligned.m16n8k32.row.col.f32.e4m3.e4m3.f32 " \
        "{%0,%1,%2,%3}, {%4,%5,%6,%7}, {%8,%9}, {%0,%1,%2,%3};" \
        : "+f"((d)[0]), "+f"((d)[1]), "+f"((d)[2]), "+f"((d)[3]) \
        : "r"(a0), "r"(a1), "r"(a2), "r"(a3), "r"(b0), "r"(b1))

__device__ __forceinline__ uint32_t f2_to_fp8x2(float a, float b) {
    return (uint32_t)__nv_cvt_float2_to_fp8x2(make_float2(a, b), __NV_SATFINITE, __NV_E4M3);
}

// Probe W dtype from its first 64 elements (e4m3 values are exact in f32/bf16).
__device__ __forceinline__ int probe_wfmt(const unsigned char* __restrict__ w) {
    const uint32_t* p32 = reinterpret_cast<const uint32_t*>(w);
    bool f32ok = true;
    #pragma unroll 4
    for (int i = 0; i < 64; i++) {
        uint32_t b = p32[i];
        float a = fabsf(__uint_as_float(b));
        if (a != 0.0f) {
            if ((b & 0xFFFFFu) != 0u || a > 448.0f || a < 0.001953125f) { f32ok = false; break; }
        }
    }
    if (f32ok) return 1;
    const uint16_t* p16 = reinterpret_cast<const uint16_t*>(w);
    bool bf16ok = true;
    #pragma unroll 4
    for (int i = 0; i < 64; i++) {
        uint16_t b = p16[i];
        uint16_t m = (uint16_t)(b & 0x7FFFu);
        if (m != 0) {
            if ((b & 0xFu) != 0u || m > 0x43E0u || m < 0x3B00u) { bf16ok = false; break; }
        }
    }
    return bf16ok ? 2 : 0;
}

// ----------------------------------------------------------------------------
// Fused prep kernel: blocks [0, T) quantize x rows; blocks [T, T+nR) repack W.
// Read-once inputs use streaming loads (__ldcs) so they don't evict the
// g_xq/g_wq scratch the GEMM is about to re-read from L2.
// ----------------------------------------------------------------------------
__global__ void __launch_bounds__(256) prep_kernel(const float* __restrict__ x,
                                                   const unsigned char* __restrict__ w,
                                                   int K, int T) {
    const int tid = threadIdx.x;

    if ((int)blockIdx.x < T) {
        const int t = blockIdx.x;
        const float4* xr = reinterpret_cast<const float4*>(x + (size_t)t * K);

        float4 v[4];
        float amax = 0.f;
        #pragma unroll
        for (int i = 0; i < 4; i++) {
            v[i] = __ldcs(xr + tid + (i << 8));
            amax = fmaxf(amax, fmaxf(fmaxf(fabsf(v[i].x), fabsf(v[i].y)),
                                     fmaxf(fabsf(v[i].z), fabsf(v[i].w))));
        }
        #pragma unroll
        for (int o = 16; o > 0; o >>= 1)
            amax = fmaxf(amax, __shfl_xor_sync(0xFFFFFFFFu, amax, o));

        __shared__ float red[8];
        __shared__ float s_scale;
        if ((tid & 31) == 0) red[tid >> 5] = amax;
        __syncthreads();
        if (tid < 32) {
            float a = (tid < 8) ? red[tid] : 0.f;
            #pragma unroll
            for (int o = 4; o > 0; o >>= 1)
                a = fmaxf(a, __shfl_xor_sync(0xFFFFFFFFu, a, o));
            if (tid == 0) {
                float s = fmaxf(a / E4M3_MAX, 1e-12f);
                g_scale[t] = s;
                s_scale = s;
            }
        }
        __syncthreads();
        const float s = s_scale;

        uint32_t* dst = reinterpret_cast<uint32_t*>(g_xq) + (size_t)t * (K >> 2);
        #pragma unroll
        for (int i = 0; i < 4; i++) {
            uint32_t p0 = f2_to_fp8x2(v[i].x / s, v[i].y / s);
            uint32_t p1 = f2_to_fp8x2(v[i].z / s, v[i].w / s);
            dst[tid + (i << 8)] = p0 | (p1 << 16);
        }
    } else {
        __shared__ int s_fmt;
        if (tid == 0) s_fmt = probe_wfmt(w);
        __syncthreads();
        const int fmt = s_fmt;

        const size_t i = (size_t)(blockIdx.x - T) * 256 + tid;  // 16-elem group
        uint4 o;
        if (fmt == 1) {
            const float4* sp = reinterpret_cast<const float4*>(w) + 4 * i;
            float4 f0 = __ldcs(sp + 0), f1 = __ldcs(sp + 1);
            float4 f2 = __ldcs(sp + 2), f3 = __ldcs(sp + 3);
            o.x = f2_to_fp8x2(f0.x, f0.y) | (f2_to_fp8x2(f0.z, f0.w) << 16);
            o.y = f2_to_fp8x2(f1.x, f1.y) | (f2_to_fp8x2(f1.z, f1.w) << 16);
            o.z = f2_to_fp8x2(f2.x, f2.y) | (f2_to_fp8x2(f2.z, f2.w) << 16);
            o.w = f2_to_fp8x2(f3.x, f3.y) | (f2_to_fp8x2(f3.z, f3.w) << 16);
        } else if (fmt == 2) {
            const uint4* sp = reinterpret_cast<const uint4*>(w) + 2 * i;
            uint4 b0 = __ldcs(sp + 0), b1 = __ldcs(sp + 1);
            const __nv_bfloat162* h0 = reinterpret_cast<const __nv_bfloat162*>(&b0);
            const __nv_bfloat162* h1 = reinterpret_cast<const __nv_bfloat162*>(&b1);
            float2 f;
            uint32_t r[8];
            #pragma unroll
            for (int j = 0; j < 4; j++) { f = __bfloat1622float2(h0[j]); r[j]     = f2_to_fp8x2(f.x, f.y); }
            #pragma unroll
            for (int j = 0; j < 4; j++) { f = __bfloat1622float2(h1[j]); r[4 + j] = f2_to_fp8x2(f.x, f.y); }
            o.x = r[0] | (r[1] << 16);
            o.y = r[2] | (r[3] << 16);
            o.z = r[4] | (r[5] << 16);
            o.w = r[6] | (r[7] << 16);
        } else {
            o = __ldcs(reinterpret_cast<const uint4*>(w) + i);
        }
        reinterpret_cast<uint4*>(g_wq)[i] = o;
    }
}

// ----------------------------------------------------------------------------
// Kernel 2 (R9 verbatim): fp8 QMMA GEMM. 128x128 tile, BK=64 fp8 (64B rows),
// 4-stage cp.async pipeline, 256 threads = 8 warps (2m x 4n), warp tile
// 64x32, 2 CTAs/SM, kt-loop unrolled x4 (immediate stage offsets).
// ----------------------------------------------------------------------------
static constexpr int F_STAGES = 4;
static constexpr int F_AST    = 128 * 64;                   // 8192 B/stage
static constexpr int F_SA     = 0;
static constexpr int F_SB     = F_STAGES * F_AST;           // 32768
static constexpr int F_SWS    = F_SB + F_STAGES * F_AST;    // 65536
static constexpr int F_SBIAS  = F_SWS + 512;                // 66048
static constexpr int F_SMEM   = F_SBIAS + 512;              // 66560

__global__ void __launch_bounds__(256, 2) mma_gemm_kernel(
    const float* __restrict__ wscale,
    const float* __restrict__ bias,
    float* __restrict__ out,
    int T, int N, int K)
{
    extern __shared__ char smem[];
    const uint32_t sbase = smem_u32(smem);
    const int tid = threadIdx.x, lane = tid & 31, wid = tid >> 5;
    const int n0 = blockIdx.x * 128, m0 = blockIdx.y * 128;
    const int m_off = (wid >> 2) * 64;   // 0 / 64
    const int n_off = (wid & 3) * 32;    // 0 / 32 / 64 / 96

    if (tid < 128) {
        reinterpret_cast<float*>(smem + F_SWS)[tid]   = wscale[n0 + tid];
        reinterpret_cast<float*>(smem + F_SBIAS)[tid] = bias[n0 + tid];
    }

    const unsigned char* aG = g_xq + (size_t)m0 * K;
    const unsigned char* bG = g_wq + (size_t)n0 * K;

    // ldmatrix x4 base addresses for ko=0; ko=1 is base ^ 32
    // (SWZ64(x+32) == SWZ64(x)^32: bit 5 of the unswizzled base is 0).
    const int rsel = lane & 15;
    const int csel = (lane >> 4) * 16;
    uint32_t preA[4], preB[2];
    #pragma unroll
    for (int mt = 0; mt < 4; mt++)
        preA[mt] = sbase + F_SA +
            SWZ64((uint32_t)((m_off + mt * 16 + rsel) * 64 + csel));
    #pragma unroll
    for (int bp = 0; bp < 2; bp++)
        preB[bp] = sbase + F_SB +
            SWZ64((uint32_t)((n_off + bp * 16 + rsel) * 64 + csel));

    float acc[4][4][4];
    #pragma unroll
    for (int i = 0; i < 4; i++)
        #pragma unroll
        for (int j = 0; j < 4; j++)
            #pragma unroll
            for (int q = 0; q < 4; q++) acc[i][j][q] = 0.f;

    const int cchunk = tid & 3;       // 16B chunk within 64B row
    const int crow   = tid >> 2;      // 0..63
    const uint32_t so0 = SWZ64((uint32_t)(crow * 64 + cchunk * 16));
    const uint32_t so1 = SWZ64((uint32_t)((crow + 64) * 64 + cchunk * 16));
    const unsigned char* aP = aG + (size_t)crow * K + cchunk * 16;
    const unsigned char* bP = bG + (size_t)crow * K + cchunk * 16;
    const size_t rowK64 = (size_t)64 * K;

    auto load_stage = [&](int st, int kt) {
        const uint32_t dA = sbase + F_SA + (uint32_t)st * F_AST;
        const uint32_t dB = sbase + F_SB + (uint32_t)st * F_AST;
        const size_t g = (size_t)kt * 64;
        CP_ASYNC16(dA + so0, aP + g);
        CP_ASYNC16(dA + so1, aP + g + rowK64);
        CP_ASYNC16(dB + so0, bP + g);
        CP_ASYNC16(dB + so1, bP + g + rowK64);
    };

    const int KT = K >> 6;  // 64 chunks of 64 fp8
    load_stage(0, 0); CP_ASYNC_COMMIT();
    load_stage(1, 1); CP_ASYNC_COMMIT();
    load_stage(2, 2); CP_ASYNC_COMMIT();

    #pragma unroll 4
    for (int kt = 0; kt < KT; kt++) {
        CP_ASYNC_WAIT2();
        __syncthreads();   // stage kt ready; all warps consumed stage kt-1
        const uint32_t stOff = (uint32_t)(kt & 3) * F_AST;  // immediate after unroll

        #pragma unroll
        for (int ko = 0; ko < 2; ko++) {
            const uint32_t koX = (uint32_t)(ko << 5);   // XOR 32 selects k-half
            uint32_t b[4][2];
            #pragma unroll
            for (int bp = 0; bp < 2; bp++) {
                uint32_t r0, r1, r2, r3;
                LDSM_X4(r0, r1, r2, r3, (preB[bp] ^ koX) + stOff);
                b[2*bp][0]   = r0; b[2*bp][1]   = r2;
                b[2*bp+1][0] = r1; b[2*bp+1][1] = r3;
            }
            #pragma unroll
            for (int mt = 0; mt < 4; mt++) {
                uint32_t a0, a1, a2, a3;
                LDSM_X4(a0, a1, a2, a3, (preA[mt] ^ koX) + stOff);
                #pragma unroll
                for (int nt = 0; nt < 4; nt++)
                    MMA_E4M3(acc[mt][nt], a0, a1, a2, a3, b[nt][0], b[nt][1]);
            }
        }

        if (kt + 3 < KT) load_stage((kt + 3) & 3, kt + 3);
        CP_ASYNC_COMMIT();
    }

    // Epilogue: acc * in_scale[row] * w_scale[col] + bias[col]
    const float* sWSp = reinterpret_cast<const float*>(smem + F_SWS);
    const float* sBiP = reinterpret_cast<const float*>(smem + F_SBIAS);
    #pragma unroll
    for (int mt = 0; mt < 4; mt++) {
        const int r0g = m0 + m_off + mt * 16 + (lane >> 2);
        const int r1g = r0g + 8;
        const float i0 = g_scale[r0g];
        const float i1 = g_scale[r1g];
        float* o0 = out + (size_t)r0g * N + n0;
        float* o1 = out + (size_t)r1g * N + n0;
        #pragma unroll
        for (int nt = 0; nt < 4; nt++) {
            const int c = n_off + nt * 8 + (lane & 3) * 2;
            const float ws0 = sWSp[c], ws1 = sWSp[c + 1];
            const float bb0 = sBiP[c], bb1 = sBiP[c + 1];
            float2 v0 = make_float2(acc[mt][nt][0] * i0 * ws0 + bb0,
                                    acc[mt][nt][1] * i0 * ws1 + bb1);
            float2 v1 = make_float2(acc[mt][nt][2] * i1 * ws0 + bb0,
                                    acc[mt][nt][3] * i1 * ws1 + bb1);
            *reinterpret_cast<float2*>(o0 + c) = v0;
            *reinterpret_cast<float2*>(o1 + c) = v1;
        }
    }
}

// ----------------------------------------------------------------------------
// Launch
// ----------------------------------------------------------------------------
extern "C" void kernel_launch(void* const* d_in, const int* in_sizes, int n_in,
                              void* d_out, int out_size) {
    const float*         x      = (const float*)d_in[0];
    const unsigned char* wraw   = (const unsigned char*)d_in[1];
    const float*         wscale = (const float*)d_in[2];
    const float*         bias   = (const float*)d_in[3];
    float*               out    = (float*)d_out;

    const int N = in_sizes[2];                     // 4096
    const int K = in_sizes[1] / N;                 // 4096
    const int T = (int)((size_t)in_sizes[0] / K);  // 8192

    const unsigned nRepack = (unsigned)(((size_t)N * K) / 16 / 256);  // 4096
    prep_kernel<<<(unsigned)T + nRepack, 256>>>(x, wraw, K, T);

    cudaFuncSetAttribute(mma_gemm_kernel, cudaFuncAttributeMaxDynamicSharedMemorySize, F_SMEM);
    dim3 grid(N / 128, T / 128);
    mma_gemm_kernel<<<grid, 256, F_SMEM>>>(wscale, bias, out, T, N, K);
}

// round 17
// speedup vs baseline: 2.0514x; 1.0191x over previous
#include <cuda_runtime.h>
#include <cuda_bf16.h>
#include <cuda_fp8.h>
#include <cstdint>

// ============================================================================
// out[T,N] = (fp8_rowwise_quant(x) @ W_fp8^T) * in_scale * w_scale + bias
// T=8192, N=4096, K=4096. Target plain sm_103.
// e4m3 QMMA m16n8k32 + f32 acc. R17 = R16 (best: 752us) + mid-window
// prefetch (lookahead starts half a window earlier, LSU spread away from
// post-barrier LDSM burst) + streaming epilogue stores (__stcs: out is
// write-once, protect g_xq/g_wq L2 residency).
// ============================================================================

#define E4M3_MAX 448.0f

static constexpr int MAX_T = 8192;
static constexpr int MAX_K = 4096;
static constexpr int MAX_N = 4096;

// Scratch (allocation-free rule: __device__ globals)
__device__ __align__(16) unsigned char g_xq[(size_t)MAX_T * MAX_K];  // 32 MB fp8
__device__ __align__(16) unsigned char g_wq[(size_t)MAX_N * MAX_K];  // 16 MB fp8
__device__ float g_scale[MAX_T];

// ----------------------------------------------------------------------------
// Helpers
// ----------------------------------------------------------------------------
__device__ __forceinline__ uint32_t smem_u32(const void* p) {
    uint32_t a;
    asm("{ .reg .u64 t; cvta.to.shared.u64 t, %1; cvt.u32.u64 %0, t; }" : "=r"(a) : "l"(p));
    return a;
}

// 64B-row swizzle: offset bits [5:4] ^= bits [8:7]
#define SWZ64(x) ((x) ^ (((x) >> 3) & 0x30))

#define CP_ASYNC16(dst, src) \
    asm volatile("cp.async.cg.shared.global [%0], [%1], 16;" :: "r"(dst), "l"(src) : "memory")
#define CP_ASYNC_COMMIT() asm volatile("cp.async.commit_group;" ::: "memory")
#define CP_ASYNC_WAIT2()  asm volatile("cp.async.wait_group 2;" ::: "memory")

#define LDSM_X4(r0, r1, r2, r3, addr) \
    asm volatile("ldmatrix.sync.aligned.m8n8.x4.shared.b16 {%0,%1,%2,%3}, [%4];" \
        : "=r"(r0), "=r"(r1), "=r"(r2), "=r"(r3) : "r"(addr))

#define MMA_E4M3(d, a0, a1, a2, a3, b0, b1) \
    asm volatile("mma.sync.aligned.m16n8k32.row.col.f32.e4m3.e4m3.f32 " \
        "{%0,%1,%2,%3}, {%4,%5,%6,%7}, {%8,%9}, {%0,%1,%2,%3};" \
        : "+f"((d)[0]), "+f"((d)[1]), "+f"((d)[2]), "+f"((d)[3]) \
        : "r"(a0), "r"(a1), "r"(a2), "r"(a3), "r"(b0), "r"(b1))

__device__ __forceinline__ uint32_t f2_to_fp8x2(float a, float b) {
    return (uint32_t)__nv_cvt_float2_to_fp8x2(make_float2(a, b), __NV_SATFINITE, __NV_E4M3);
}

// Probe W dtype from its first 64 elements (e4m3 values are exact in f32/bf16).
__device__ __forceinline__ int probe_wfmt(const unsigned char* __restrict__ w) {
    const uint32_t* p32 = reinterpret_cast<const uint32_t*>(w);
    bool f32ok = true;
    #pragma unroll 4
    for (int i = 0; i < 64; i++) {
        uint32_t b = p32[i];
        float a = fabsf(__uint_as_float(b));
        if (a != 0.0f) {
            if ((b & 0xFFFFFu) != 0u || a > 448.0f || a < 0.001953125f) { f32ok = false; break; }
        }
    }
    if (f32ok) return 1;
    const uint16_t* p16 = reinterpret_cast<const uint16_t*>(w);
    bool bf16ok = true;
    #pragma unroll 4
    for (int i = 0; i < 64; i++) {
        uint16_t b = p16[i];
        uint16_t m = (uint16_t)(b & 0x7FFFu);
        if (m != 0) {
            if ((b & 0xFu) != 0u || m > 0x43E0u || m < 0x3B00u) { bf16ok = false; break; }
        }
    }
    return bf16ok ? 2 : 0;
}

// ----------------------------------------------------------------------------
// Fused prep kernel: blocks [0, T) quantize x rows; blocks [T, T+nR) repack W.
// Read-once inputs use streaming loads (__ldcs).
// ----------------------------------------------------------------------------
__global__ void __launch_bounds__(256) prep_kernel(const float* __restrict__ x,
                                                   const unsigned char* __restrict__ w,
                                                   int K, int T) {
    const int tid = threadIdx.x;

    if ((int)blockIdx.x < T) {
        const int t = blockIdx.x;
        const float4* xr = reinterpret_cast<const float4*>(x + (size_t)t * K);

        float4 v[4];
        float amax = 0.f;
        #pragma unroll
        for (int i = 0; i < 4; i++) {
            v[i] = __ldcs(xr + tid + (i << 8));
            amax = fmaxf(amax, fmaxf(fmaxf(fabsf(v[i].x), fabsf(v[i].y)),
                                     fmaxf(fabsf(v[i].z), fabsf(v[i].w))));
        }
        #pragma unroll
        for (int o = 16; o > 0; o >>= 1)
            amax = fmaxf(amax, __shfl_xor_sync(0xFFFFFFFFu, amax, o));

        __shared__ float red[8];
        __shared__ float s_scale;
        if ((tid & 31) == 0) red[tid >> 5] = amax;
        __syncthreads();
        if (tid < 32) {
            float a = (tid < 8) ? red[tid] : 0.f;
            #pragma unroll
            for (int o = 4; o > 0; o >>= 1)
                a = fmaxf(a, __shfl_xor_sync(0xFFFFFFFFu, a, o));
            if (tid == 0) {
                float s = fmaxf(a / E4M3_MAX, 1e-12f);
                g_scale[t] = s;
                s_scale = s;
            }
        }
        __syncthreads();
        const float s = s_scale;

        uint32_t* dst = reinterpret_cast<uint32_t*>(g_xq) + (size_t)t * (K >> 2);
        #pragma unroll
        for (int i = 0; i < 4; i++) {
            uint32_t p0 = f2_to_fp8x2(v[i].x / s, v[i].y / s);
            uint32_t p1 = f2_to_fp8x2(v[i].z / s, v[i].w / s);
            dst[tid + (i << 8)] = p0 | (p1 << 16);
        }
    } else {
        __shared__ int s_fmt;
        if (tid == 0) s_fmt = probe_wfmt(w);
        __syncthreads();
        const int fmt = s_fmt;

        const size_t i = (size_t)(blockIdx.x - T) * 256 + tid;  // 16-elem group
        uint4 o;
        if (fmt == 1) {
            const float4* sp = reinterpret_cast<const float4*>(w) + 4 * i;
            float4 f0 = __ldcs(sp + 0), f1 = __ldcs(sp + 1);
            float4 f2 = __ldcs(sp + 2), f3 = __ldcs(sp + 3);
            o.x = f2_to_fp8x2(f0.x, f0.y) | (f2_to_fp8x2(f0.z, f0.w) << 16);
            o.y = f2_to_fp8x2(f1.x, f1.y) | (f2_to_fp8x2(f1.z, f1.w) << 16);
            o.z = f2_to_fp8x2(f2.x, f2.y) | (f2_to_fp8x2(f2.z, f2.w) << 16);
            o.w = f2_to_fp8x2(f3.x, f3.y) | (f2_to_fp8x2(f3.z, f3.w) << 16);
        } else if (fmt == 2) {
            const uint4* sp = reinterpret_cast<const uint4*>(w) + 2 * i;
            uint4 b0 = __ldcs(sp + 0), b1 = __ldcs(sp + 1);
            const __nv_bfloat162* h0 = reinterpret_cast<const __nv_bfloat162*>(&b0);
            const __nv_bfloat162* h1 = reinterpret_cast<const __nv_bfloat162*>(&b1);
            float2 f;
            uint32_t r[8];
            #pragma unroll
            for (int j = 0; j < 4; j++) { f = __bfloat1622float2(h0[j]); r[j]     = f2_to_fp8x2(f.x, f.y); }
            #pragma unroll
            for (int j = 0; j < 4; j++) { f = __bfloat1622float2(h1[j]); r[4 + j] = f2_to_fp8x2(f.x, f.y); }
            o.x = r[0] | (r[1] << 16);
            o.y = r[2] | (r[3] << 16);
            o.z = r[4] | (r[5] << 16);
            o.w = r[6] | (r[7] << 16);
        } else {
            o = __ldcs(reinterpret_cast<const uint4*>(w) + i);
        }
        reinterpret_cast<uint4*>(g_wq)[i] = o;
    }
}

// ----------------------------------------------------------------------------
// Kernel 2: fp8 QMMA GEMM. 128x128 tile, BK=64 fp8 (64B rows), 4-stage
// cp.async pipeline, 256 threads = 8 warps (2m x 4n), warp tile 64x32,
// 2 CTAs/SM, kt-loop unrolled x4, mid-window prefetch, streaming out stores.
// ----------------------------------------------------------------------------
static constexpr int F_STAGES = 4;
static constexpr int F_AST    = 128 * 64;                   // 8192 B/stage
static constexpr int F_SA     = 0;
static constexpr int F_SB     = F_STAGES * F_AST;           // 32768
static constexpr int F_SWS    = F_SB + F_STAGES * F_AST;    // 65536
static constexpr int F_SBIAS  = F_SWS + 512;                // 66048
static constexpr int F_SMEM   = F_SBIAS + 512;              // 66560

__global__ void __launch_bounds__(256, 2) mma_gemm_kernel(
    const float* __restrict__ wscale,
    const float* __restrict__ bias,
    float* __restrict__ out,
    int T, int N, int K)
{
    extern __shared__ char smem[];
    const uint32_t sbase = smem_u32(smem);
    const int tid = threadIdx.x, lane = tid & 31, wid = tid >> 5;
    const int n0 = blockIdx.x * 128, m0 = blockIdx.y * 128;
    const int m_off = (wid >> 2) * 64;   // 0 / 64
    const int n_off = (wid & 3) * 32;    // 0 / 32 / 64 / 96

    if (tid < 128) {
        reinterpret_cast<float*>(smem + F_SWS)[tid]   = wscale[n0 + tid];
        reinterpret_cast<float*>(smem + F_SBIAS)[tid] = bias[n0 + tid];
    }

    const unsigned char* aG = g_xq + (size_t)m0 * K;
    const unsigned char* bG = g_wq + (size_t)n0 * K;

    // ldmatrix x4 base addresses for ko=0; ko=1 is base ^ 32
    // (SWZ64(x+32) == SWZ64(x)^32: bit 5 of the unswizzled base is 0).
    const int rsel = lane & 15;
    const int csel = (lane >> 4) * 16;
    uint32_t preA[4], preB[2];
    #pragma unroll
    for (int mt = 0; mt < 4; mt++)
        preA[mt] = sbase + F_SA +
            SWZ64((uint32_t)((m_off + mt * 16 + rsel) * 64 + csel));
    #pragma unroll
    for (int bp = 0; bp < 2; bp++)
        preB[bp] = sbase + F_SB +
            SWZ64((uint32_t)((n_off + bp * 16 + rsel) * 64 + csel));

    float acc[4][4][4];
    #pragma unroll
    for (int i = 0; i < 4; i++)
        #pragma unroll
        for (int j = 0; j < 4; j++)
            #pragma unroll
            for (int q = 0; q < 4; q++) acc[i][j][q] = 0.f;

    const int cchunk = tid & 3;       // 16B chunk within 64B row
    const int crow   = tid >> 2;      // 0..63
    const uint32_t so0 = SWZ64((uint32_t)(crow * 64 + cchunk * 16));
    const uint32_t so1 = SWZ64((uint32_t)((crow + 64) * 64 + cchunk * 16));
    const unsigned char* aP = aG + (size_t)crow * K + cchunk * 16;
    const unsigned char* bP = bG + (size_t)crow * K + cchunk * 16;
    const size_t rowK64 = (size_t)64 * K;

    auto load_stage = [&](int st, int kt) {
        const uint32_t dA = sbase + F_SA + (uint32_t)st * F_AST;
        const uint32_t dB = sbase + F_SB + (uint32_t)st * F_AST;
        const size_t g = (size_t)kt * 64;
        CP_ASYNC16(dA + so0, aP + g);
        CP_ASYNC16(dA + so1, aP + g + rowK64);
        CP_ASYNC16(dB + so0, bP + g);
        CP_ASYNC16(dB + so1, bP + g + rowK64);
    };

    auto compute_half = [&](uint32_t stOff, int ko) {
        const uint32_t koX = (uint32_t)(ko << 5);   // XOR 32 selects k-half
        uint32_t b[4][2];
        #pragma unroll
        for (int bp = 0; bp < 2; bp++) {
            uint32_t r0, r1, r2, r3;
            LDSM_X4(r0, r1, r2, r3, (preB[bp] ^ koX) + stOff);
            b[2*bp][0]   = r0; b[2*bp][1]   = r2;
            b[2*bp+1][0] = r1; b[2*bp+1][1] = r3;
        }
        #pragma unroll
        for (int mt = 0; mt < 4; mt++) {
            uint32_t a0, a1, a2, a3;
            LDSM_X4(a0, a1, a2, a3, (preA[mt] ^ koX) + stOff);
            #pragma unroll
            for (int nt = 0; nt < 4; nt++)
                MMA_E4M3(acc[mt][nt], a0, a1, a2, a3, b[nt][0], b[nt][1]);
        }
    };

    const int KT = K >> 6;  // 64 chunks of 64 fp8
    load_stage(0, 0); CP_ASYNC_COMMIT();
    load_stage(1, 1); CP_ASYNC_COMMIT();
    load_stage(2, 2); CP_ASYNC_COMMIT();

    #pragma unroll 4
    for (int kt = 0; kt < KT; kt++) {
        CP_ASYNC_WAIT2();
        __syncthreads();   // stage kt ready; all warps consumed stage kt-1
        const uint32_t stOff = (uint32_t)(kt & 3) * F_AST;  // immediate after unroll

        compute_half(stOff, 0);
        // Mid-window prefetch: lookahead starts ~half a window earlier and
        // LSU issue is spread away from the post-barrier LDSM burst.
        if (kt + 3 < KT) load_stage((kt + 3) & 3, kt + 3);
        compute_half(stOff, 1);
        CP_ASYNC_COMMIT();
    }

    // Epilogue: acc * in_scale[row] * w_scale[col] + bias[col].
    // out is write-once -> streaming stores protect g_xq/g_wq L2 residency.
    const float* sWSp = reinterpret_cast<const float*>(smem + F_SWS);
    const float* sBiP = reinterpret_cast<const float*>(smem + F_SBIAS);
    #pragma unroll
    for (int mt = 0; mt < 4; mt++) {
        const int r0g = m0 + m_off + mt * 16 + (lane >> 2);
        const int r1g = r0g + 8;
        const float i0 = g_scale[r0g];
        const float i1 = g_scale[r1g];
        float* o0 = out + (size_t)r0g * N + n0;
        float* o1 = out + (size_t)r1g * N + n0;
        #pragma unroll
        for (int nt = 0; nt < 4; nt++) {
            const int c = n_off + nt * 8 + (lane & 3) * 2;
            const float ws0 = sWSp[c], ws1 = sWSp[c + 1];
            const float bb0 = sBiP[c], bb1 = sBiP[c + 1];
            float2 v0 = make_float2(acc[mt][nt][0] * i0 * ws0 + bb0,
                                    acc[mt][nt][1] * i0 * ws1 + bb1);
            float2 v1 = make_float2(acc[mt][nt][2] * i1 * ws0 + bb0,
                                    acc[mt][nt][3] * i1 * ws1 + bb1);
            __stcs(reinterpret_cast<float2*>(o0 + c), v0);
            __stcs(reinterpret_cast<float2*>(o1 + c), v1);
        }
    }
}

// ----------------------------------------------------------------------------
// Launch
// ----------------------------------------------------------------------------
extern "C" void kernel_launch(void* const* d_in, const int* in_sizes, int n_in,
                              void* d_out, int out_size) {
    const float*         x      = (const float*)d_in[0];
    const unsigned char* wraw   = (const unsigned char*)d_in[1];
    const float*         wscale = (const float*)d_in[2];
    const float*         bias   = (const float*)d_in[3];
    float*               out    = (float*)d_out;

    const int N = in_sizes[2];                     // 4096
    const int K = in_sizes[1] / N;                 // 4096
    const int T = (int)((size_t)in_sizes[0] / K);  // 8192

    const unsigned nRepack = (unsigned)(((size_t)N * K) / 16 / 256);  // 4096
    prep_kernel<<<(unsigned)T + nRepack, 256>>>(x, wraw, K, T);

    cudaFuncSetAttribute(mma_gemm_kernel, cudaFuncAttributeMaxDynamicSharedMemorySize, F_SMEM);
    dim3 grid(N / 128, T / 128);
    mma_gemm_kernel<<<grid, 256, F_SMEM>>>(wscale, bias, out, T, N, K);
}